// round 14
// baseline (speedup 1.0000x reference)
#include <cuda_runtime.h>
#include <math.h>
#include <stdint.h>

// Problem shape
#define QN 8192
#define KN 1024
#define DN 1024
#define EPSF 1e-6f

// Tiling
#define BM 128
#define BN 128
#define BKC 64                  // int8 k-elems per chunk (64 bytes per row)
#define NCH (DN / BKC)          // 16 chunks
#define NPART 32                // 8 col tiles * 4 warp_n

// SMEM: 64B rows, XOR-swizzled 16B segments (conflict-free ldmatrix)
#define TILE_B 8192             // 128 rows x 64B
#define STAGE_B (4 * TILE_B)    // q1A, q0A, q1B, q0B
#define SM_QSQ 0
#define SM_QSM 512
#define SM_PSQ 1024
#define SM_PSM 1536
#define SM_SA  2048
#define SM_SB  2560
#define SM_TILES 3072
#define SMEM_TOTAL (SM_TILES + 3 * STAGE_B)   // 101376 -> 2 CTAs/SM

// swizzled 16B-segment offset within a tile
__device__ __forceinline__ uint32_t swz(int row, int seg) {
    return (uint32_t)(row * 64 + ((seg ^ ((row >> 1) & 3)) << 4));
}

// ---- allocation-free scratch ----
__device__ uint32_t g_Qq1[(size_t)QN * DN / 4];
__device__ uint32_t g_Qq0[(size_t)QN * DN / 4];
__device__ uint32_t g_Pq1[(size_t)KN * DN / 4];
__device__ uint32_t g_Pq0[(size_t)KN * DN / 4];
__device__ float g_qsq[QN];
__device__ float g_qsum[QN];
__device__ float g_qsc[QN];
__device__ float g_psq[KN];
__device__ float g_psum[KN];
__device__ float g_psc[KN];
__device__ float g_Spart[(size_t)QN * NPART];
__device__ float g_Upart[(size_t)QN * NPART];
__device__ float g_Mpart[(size_t)QN * NPART];

// ---- PTX helpers ----
__device__ __forceinline__ uint32_t smem_to_u32(const void* p) {
    uint32_t a;
    asm("{ .reg .u64 t; cvta.to.shared.u64 t, %1; cvt.u32.u64 %0, t; }" : "=r"(a) : "l"(p));
    return a;
}
__device__ __forceinline__ void cp16(uint32_t dst, const void* src) {
    asm volatile("cp.async.ca.shared.global [%0], [%1], 16;" :: "r"(dst), "l"(src));
}
#define CP_COMMIT() asm volatile("cp.async.commit_group;" ::: "memory")
#define CP_WAIT(n)  asm volatile("cp.async.wait_group %0;" :: "n"(n) : "memory")

__device__ __forceinline__ void ldm_x4(uint32_t* r, uint32_t addr) {
    asm volatile("ldmatrix.sync.aligned.m8n8.x4.shared.b16 {%0,%1,%2,%3}, [%4];"
        : "=r"(r[0]), "=r"(r[1]), "=r"(r[2]), "=r"(r[3]) : "r"(addr));
}
__device__ __forceinline__ void imma(int* d, const uint32_t* a, uint32_t b0, uint32_t b1) {
    asm volatile("mma.sync.aligned.m16n8k32.row.col.s32.s8.s8.s32 "
        "{%0,%1,%2,%3}, {%4,%5,%6,%7}, {%8,%9}, {%0,%1,%2,%3};"
        : "+r"(d[0]), "+r"(d[1]), "+r"(d[2]), "+r"(d[3])
        : "r"(a[0]), "r"(a[1]), "r"(a[2]), "r"(a[3]), "r"(b0), "r"(b1));
}

// ============================================================
// 1) Quantize fp32 -> int8 two-limb (per-row scale) + row stats.
//    One warp per row; stats computed in exact fp32.
// ============================================================
__global__ __launch_bounds__(256) void convert_stats_kernel(const float* __restrict__ Qf,
                                                            const float* __restrict__ Pf) {
    int warp = (blockIdx.x * blockDim.x + threadIdx.x) >> 5;
    int lane = threadIdx.x & 31;
    if (warp >= QN + KN) return;

    bool isQ = warp < QN;
    int row = isQ ? warp : warp - QN;
    size_t roff = (size_t)row * DN;
    const float* src = (isQ ? Qf : Pf) + roff;
    uint32_t* q1 = (isQ ? g_Qq1 : g_Pq1) + roff / 4;
    uint32_t* q0 = (isQ ? g_Qq0 : g_Pq0) + roff / 4;

    float s1 = 0.f, s2 = 0.f, mx = 0.f;
    #pragma unroll
    for (int it = 0; it < DN / 128; it++) {
        int d = it * 128 + lane * 4;
        float4 v = *(const float4*)(src + d);
        s2 += v.x * v.x + v.y * v.y + v.z * v.z + v.w * v.w;
        s1 += v.x + v.y + v.z + v.w;
        mx = fmaxf(mx, fmaxf(fmaxf(fabsf(v.x), fabsf(v.y)), fmaxf(fabsf(v.z), fabsf(v.w))));
    }
    #pragma unroll
    for (int o = 16; o > 0; o >>= 1) {
        s2 += __shfl_xor_sync(0xFFFFFFFFu, s2, o);
        s1 += __shfl_xor_sync(0xFFFFFFFFu, s1, o);
        mx = fmaxf(mx, __shfl_xor_sync(0xFFFFFFFFu, mx, o));
    }
    const float invs = (mx > 0.f) ? (127.0f / mx) : 0.f;

    #pragma unroll
    for (int it = 0; it < DN / 128; it++) {
        int d = it * 128 + lane * 4;
        float4 v = *(const float4*)(src + d);
        uint32_t p1 = 0, p0 = 0;
        #pragma unroll
        for (int j = 0; j < 4; j++) {
            float a = ((const float*)&v)[j];
            float t = a * invs;
            float f1 = rintf(t);
            float e = t - f1;
            float f0 = fminf(fmaxf(rintf(e * 256.0f), -127.0f), 127.0f);
            int i1 = (int)f1, i0 = (int)f0;
            p1 |= ((uint32_t)(i1 & 0xFF)) << (8 * j);
            p0 |= ((uint32_t)(i0 & 0xFF)) << (8 * j);
        }
        q1[d >> 2] = p1;
        q0[d >> 2] = p0;
    }
    if (lane == 0) {
        if (isQ) { g_qsq[row] = s2; g_qsum[row] = s1; g_qsc[row] = mx * (1.0f / 127.0f); }
        else     { g_psq[row] = s2; g_psum[row] = s1; g_psc[row] = mx * (1.0f / 127.0f); }
    }
}

// load one 128x64B int8 tile (chunk ch) into swizzled SMEM (1 cp16/thread)
__device__ __forceinline__ void load_tile(uint32_t dst_base, const uint32_t* src, int ch, int tid) {
    int row = tid >> 2, seg = tid & 3;
    cp16(dst_base + swz(row, seg),
         src + (size_t)row * (DN / 4) + ch * (BKC / 4) + seg * 4);
}

// ============================================================
// 2) int8 two-limb GEMM via mma.sync.m16n8k32.s8 + fused epilogue.
//    grid=(KN/BN, QN/BM), 512 threads (16 warps, 4x4), 3-stage cp.async.
// ============================================================
__global__ void __launch_bounds__(512, 2) tc_gemm_kernel(float* __restrict__ out) {
    extern __shared__ char smem[];
    const int bx = blockIdx.x, by = blockIdx.y;
    const int tid = threadIdx.x;
    const int wid = tid >> 5, lane = tid & 31;
    const int warp_m = wid & 3;         // 32-row band
    const int warp_n = wid >> 2;        // 32-col band
    const uint32_t sb = smem_to_u32(smem);

    if (tid < 128) {
        ((float*)(smem + SM_QSQ))[tid] = g_qsq[by * BM + tid];
        ((float*)(smem + SM_QSM))[tid] = g_qsum[by * BM + tid];
        ((float*)(smem + SM_PSQ))[tid] = g_psq[bx * BN + tid];
        ((float*)(smem + SM_PSM))[tid] = g_psum[bx * BN + tid];
        ((float*)(smem + SM_SA))[tid] = g_qsc[by * BM + tid];
        ((float*)(smem + SM_SB))[tid] = g_psc[bx * BN + tid];
    }

    const uint32_t* A1 = g_Qq1 + (size_t)by * BM * (DN / 4);
    const uint32_t* A0 = g_Qq0 + (size_t)by * BM * (DN / 4);
    const uint32_t* B1 = g_Pq1 + (size_t)bx * BN * (DN / 4);
    const uint32_t* B0 = g_Pq0 + (size_t)bx * BN * (DN / 4);

    // prologue: chunks 0,1 into stages 0,1
    #pragma unroll
    for (int c = 0; c < 2; c++) {
        uint32_t st = sb + SM_TILES + c * STAGE_B;
        load_tile(st + 0 * TILE_B, A1, c, tid);
        load_tile(st + 1 * TILE_B, A0, c, tid);
        load_tile(st + 2 * TILE_B, B1, c, tid);
        load_tile(st + 3 * TILE_B, B0, c, tid);
        CP_COMMIT();
    }

    int acc11[2][4][4], accC[2][4][4];
    #pragma unroll
    for (int t = 0; t < 2; t++)
        #pragma unroll
        for (int u = 0; u < 4; u++)
            #pragma unroll
            for (int v = 0; v < 4; v++) { acc11[t][u][v] = 0; accC[t][u][v] = 0; }

    for (int ch = 0; ch < NCH; ch++) {
        if (ch + 1 < NCH) { CP_WAIT(1); } else { CP_WAIT(0); }
        __syncthreads();

        // issue next-next chunk loads (stage consumed at ch-1; sync above protects it)
        if (ch + 2 < NCH) {
            uint32_t st = sb + SM_TILES + ((ch + 2) % 3) * STAGE_B;
            load_tile(st + 0 * TILE_B, A1, ch + 2, tid);
            load_tile(st + 1 * TILE_B, A0, ch + 2, tid);
            load_tile(st + 2 * TILE_B, B1, ch + 2, tid);
            load_tile(st + 3 * TILE_B, B0, ch + 2, tid);
            CP_COMMIT();
        }

        const uint32_t base = sb + SM_TILES + (ch % 3) * STAGE_B;
        const int m = lane >> 3;            // ldmatrix sub-matrix index

        #pragma unroll
        for (int s = 0; s < 2; s++) {       // two k32 steps per 64-elem chunk
            // A fragments: per (mtile, limb), x4 = {r0-7 k0-15, r8-15 k0-15, r0-7 k16-31, r8-15 k16-31}
            uint32_t aq1[2][4], aq0[2][4];
            #pragma unroll
            for (int t = 0; t < 2; t++) {
                int arow = warp_m * 32 + t * 16 + (m & 1) * 8 + (lane & 7);
                int aseg = s * 2 + (m >> 1);
                ldm_x4(aq1[t], base + 0 * TILE_B + swz(arow, aseg));
                ldm_x4(aq0[t], base + 1 * TILE_B + swz(arow, aseg));
            }
            #pragma unroll
            for (int np = 0; np < 2; np++) {    // ntile pairs (2 ntiles per x4)
                // B x4: {nt0 k0-15, nt0 k16-31, nt1 k0-15, nt1 k16-31}
                int bcol = warp_n * 32 + np * 16 + (m >> 1) * 8 + (lane & 7);
                int bseg = s * 2 + (m & 1);
                uint32_t bq1[4], bq0[4];
                ldm_x4(bq1, base + 2 * TILE_B + swz(bcol, bseg));
                ldm_x4(bq0, base + 3 * TILE_B + swz(bcol, bseg));
                #pragma unroll
                for (int t = 0; t < 2; t++) {
                    #pragma unroll
                    for (int j = 0; j < 2; j++) {
                        const int u = np * 2 + j;
                        imma(acc11[t][u], aq1[t], bq1[2 * j], bq1[2 * j + 1]);  // q1*q1
                        imma(accC[t][u],  aq1[t], bq0[2 * j], bq0[2 * j + 1]);  // q1*q0
                        imma(accC[t][u],  aq0[t], bq1[2 * j], bq1[2 * j + 1]);  // q0*q1
                    }
                }
            }
        }
    }

    // ---------- fused epilogue ----------
    const float kconst = (float)DN * EPSF * EPSF;
    const float* sQSQ = (const float*)(smem + SM_QSQ);
    const float* sQSM = (const float*)(smem + SM_QSM);
    const float* sPSQ = (const float*)(smem + SM_PSQ);
    const float* sPSM = (const float*)(smem + SM_PSM);
    const float* sSA  = (const float*)(smem + SM_SA);
    const float* sSB  = (const float*)(smem + SM_SB);

    #pragma unroll
    for (int t = 0; t < 2; t++) {
        #pragma unroll
        for (int rr = 0; rr < 2; rr++) {
            const int rowl = warp_m * 32 + t * 16 + rr * 8 + (lane >> 2);
            const int grow = by * BM + rowl;
            const float qsq = sQSQ[rowl];
            const float qsm = sQSM[rowl];
            const float sa = sSA[rowl];
            float su = 0.f, sud = 0.f, mu = 0.f;
            float* op = out + (size_t)grow * KN + bx * BN + warp_n * 32;
            #pragma unroll
            for (int u = 0; u < 4; u++) {
                const int c0 = u * 8 + (lane & 3) * 2;
                const int gc0 = warp_n * 32 + c0;
                const float sc0 = sa * sSB[gc0];
                const float sc1 = sa * sSB[gc0 + 1];
                float cr0 = sc0 * ((float)acc11[t][u][rr * 2 + 0] + (float)accC[t][u][rr * 2 + 0] * 0.00390625f);
                float cr1 = sc1 * ((float)acc11[t][u][rr * 2 + 1] + (float)accC[t][u][rr * 2 + 1] * 0.00390625f);
                float sq0 = qsq + sPSQ[gc0]     - 2.f * cr0 + 2.f * EPSF * (qsm - sPSM[gc0])     + kconst;
                float sq1 = qsq + sPSQ[gc0 + 1] - 2.f * cr1 + 2.f * EPSF * (qsm - sPSM[gc0 + 1]) + kconst;
                float d0 = sqrtf(fmaxf(sq0, 0.f));
                float d1 = sqrtf(fmaxf(sq1, 0.f));
                float u0 = __expf(-d0);
                float u1 = __expf(-d1);
                su += u0 + u1;
                sud = fmaf(u0, d0, fmaf(u1, d1, sud));
                mu = fmaxf(mu, fmaxf(u0, u1));
                *(float2*)(op + c0) = make_float2(u0, u1);
            }
            #pragma unroll
            for (int o = 1; o <= 2; o <<= 1) {
                su  += __shfl_xor_sync(0xFFFFFFFFu, su,  o);
                sud += __shfl_xor_sync(0xFFFFFFFFu, sud, o);
                mu   = fmaxf(mu, __shfl_xor_sync(0xFFFFFFFFu, mu, o));
            }
            if ((lane & 3) == 0) {
                const size_t pidx = (size_t)grow * NPART + bx * 4 + warp_n;
                g_Spart[pidx] = su;
                g_Upart[pidx] = sud;
                g_Mpart[pidx] = mu;
            }
        }
    }
}

// ============================================================
// 3) Finalize: one block per query row, fixed-order reduction.
// ============================================================
__global__ __launch_bounds__(256) void finalize_kernel(float* __restrict__ out) {
    const int row = blockIdx.x;
    float S = 0.f, U = 0.f, Mx = 0.f;
    #pragma unroll
    for (int j = 0; j < NPART; j++) {
        S += g_Spart[(size_t)row * NPART + j];
        U += g_Upart[(size_t)row * NPART + j];
        Mx = fmaxf(Mx, g_Mpart[(size_t)row * NPART + j]);
    }
    const float invS = 1.f / S;

    float4* post4 = (float4*)(out + (size_t)row * KN);
    float4 v = post4[threadIdx.x];
    v.x *= invS; v.y *= invS; v.z *= invS; v.w *= invS;
    post4[threadIdx.x] = v;

    if (threadIdx.x == 0) {
        out[(size_t)QN * KN + row]      = Mx * invS;           // c
        out[(size_t)QN * KN + QN + row] = U * invS + logf(S);  // h
    }
}

// ============================================================
extern "C" void kernel_launch(void* const* d_in, const int* in_sizes, int n_in,
                              void* d_out, int out_size) {
    const float* P  = (const float*)d_in[0];   // class_prototypes [KN, DN]
    const float* Qf = (const float*)d_in[1];   // query_features   [QN, DN]
    float* out = (float*)d_out;

    {
        int blocks = ((QN + KN) * 32 + 255) / 256;
        convert_stats_kernel<<<blocks, 256>>>(Qf, P);
    }
    cudaFuncSetAttribute(tc_gemm_kernel, cudaFuncAttributeMaxDynamicSharedMemorySize, SMEM_TOTAL);
    {
        dim3 grid(KN / BN, QN / BM);
        tc_gemm_kernel<<<grid, 512, SMEM_TOTAL>>>(out);
    }
    finalize_kernel<<<QN, 256>>>(out);
}

// round 16
// speedup vs baseline: 2.3730x; 2.3730x over previous
#include <cuda_runtime.h>
#include <cuda_fp16.h>
#include <math.h>
#include <stdint.h>

// Problem shape
#define QN 8192
#define KN 1024
#define DN 1024
#define EPSF 1e-6f

// Tiling: CTA = 128x64, 8 warps (4x2), warp tile 32x32
#define BM 128
#define BN 64
#define BKC 32                  // fp16 k-elems per chunk (64B per row)
#define NCH (DN / BKC)          // 32 chunks
#define NPART 32                // 16 col blocks * 2 warp_n

// SMEM: 64B data rows padded to 80B stride
#define TSTRIDE 80
#define TILE_A (128 * TSTRIDE)          // 10240
#define TILE_Bb (64 * TSTRIDE)          // 5120
#define STAGE_B (2 * TILE_A + 2 * TILE_Bb)  // 30720: Ah, Al, Bh, Bl
#define SM_QSQ 0
#define SM_QSM 512
#define SM_PSQ 1024
#define SM_PSM 1280
#define SM_TILES 2048
#define SMEM_TOTAL (SM_TILES + 2 * STAGE_B)   // 63488 -> 2+ CTAs/SM

// ---- allocation-free scratch ----
__device__ unsigned short g_Qhi[(size_t)QN * DN];
__device__ unsigned short g_Qlo[(size_t)QN * DN];
__device__ unsigned short g_Phi[(size_t)KN * DN];
__device__ unsigned short g_Plo[(size_t)KN * DN];
__device__ float g_qsq[QN];
__device__ float g_qsum[QN];
__device__ float g_psq[KN];
__device__ float g_psum[KN];
__device__ float g_Spart[(size_t)QN * NPART];
__device__ float g_Upart[(size_t)QN * NPART];
__device__ float g_Mpart[(size_t)QN * NPART];

// ---- PTX helpers ----
__device__ __forceinline__ uint32_t smem_to_u32(const void* p) {
    uint32_t a;
    asm("{ .reg .u64 t; cvta.to.shared.u64 t, %1; cvt.u32.u64 %0, t; }" : "=r"(a) : "l"(p));
    return a;
}
__device__ __forceinline__ void cp16(uint32_t dst, const void* src) {
    asm volatile("cp.async.ca.shared.global [%0], [%1], 16;" :: "r"(dst), "l"(src));
}
#define CP_COMMIT() asm volatile("cp.async.commit_group;" ::: "memory")
#define CP_WAIT(n)  asm volatile("cp.async.wait_group %0;" :: "n"(n) : "memory")

__device__ __forceinline__ void ldm_x4(uint32_t* r, uint32_t addr) {
    asm volatile("ldmatrix.sync.aligned.m8n8.x4.shared.b16 {%0,%1,%2,%3}, [%4];"
        : "=r"(r[0]), "=r"(r[1]), "=r"(r[2]), "=r"(r[3]) : "r"(addr));
}
// fp16 inputs, f32 accumulate (main pass)
__device__ __forceinline__ void mma_f32(float* d, const uint32_t* a, uint32_t b0, uint32_t b1) {
    asm volatile("mma.sync.aligned.m16n8k16.row.col.f32.f16.f16.f32 "
        "{%0,%1,%2,%3}, {%4,%5,%6,%7}, {%8,%9}, {%0,%1,%2,%3};"
        : "+f"(d[0]), "+f"(d[1]), "+f"(d[2]), "+f"(d[3])
        : "r"(a[0]), "r"(a[1]), "r"(a[2]), "r"(a[3]), "r"(b0), "r"(b1));
}
// fp16 inputs, f16 accumulate (correction passes; hypothesis: 2x rate)
__device__ __forceinline__ void mma_f16(uint32_t* d, const uint32_t* a, uint32_t b0, uint32_t b1) {
    asm volatile("mma.sync.aligned.m16n8k16.row.col.f16.f16.f16.f16 "
        "{%0,%1}, {%2,%3,%4,%5}, {%6,%7}, {%0,%1};"
        : "+r"(d[0]), "+r"(d[1])
        : "r"(a[0]), "r"(a[1]), "r"(a[2]), "r"(a[3]), "r"(b0), "r"(b1));
}

// ============================================================
// 1) Convert fp32 -> fp16 hi/lo AND row stats. One warp per row.
// ============================================================
__global__ __launch_bounds__(256) void convert_stats_kernel(const float* __restrict__ Qf,
                                                            const float* __restrict__ Pf) {
    int warp = (blockIdx.x * blockDim.x + threadIdx.x) >> 5;
    int lane = threadIdx.x & 31;
    if (warp >= QN + KN) return;

    bool isQ = warp < QN;
    size_t roff = (size_t)(isQ ? warp : warp - QN) * DN;
    const float* src = (isQ ? Qf : Pf) + roff;
    unsigned short* hi = (isQ ? g_Qhi : g_Phi) + roff;
    unsigned short* lo = (isQ ? g_Qlo : g_Plo) + roff;

    float s1 = 0.f, s2 = 0.f;
    #pragma unroll
    for (int it = 0; it < DN / 128; it++) {
        int d = it * 128 + lane * 4;
        float4 v = *(const float4*)(src + d);
        s2 += v.x * v.x + v.y * v.y + v.z * v.z + v.w * v.w;
        s1 += v.x + v.y + v.z + v.w;

        __half h0 = __float2half_rn(v.x), h1 = __float2half_rn(v.y);
        __half h2 = __float2half_rn(v.z), h3 = __float2half_rn(v.w);
        __half l0 = __float2half_rn(v.x - __half2float(h0));
        __half l1 = __float2half_rn(v.y - __half2float(h1));
        __half l2 = __float2half_rn(v.z - __half2float(h2));
        __half l3 = __float2half_rn(v.w - __half2float(h3));

        uint2 hp, lp;
        hp.x = (uint32_t)__half_as_ushort(h0) | ((uint32_t)__half_as_ushort(h1) << 16);
        hp.y = (uint32_t)__half_as_ushort(h2) | ((uint32_t)__half_as_ushort(h3) << 16);
        lp.x = (uint32_t)__half_as_ushort(l0) | ((uint32_t)__half_as_ushort(l1) << 16);
        lp.y = (uint32_t)__half_as_ushort(l2) | ((uint32_t)__half_as_ushort(l3) << 16);
        *(uint2*)(hi + d) = hp;
        *(uint2*)(lo + d) = lp;
    }
    #pragma unroll
    for (int o = 16; o > 0; o >>= 1) {
        s2 += __shfl_xor_sync(0xFFFFFFFFu, s2, o);
        s1 += __shfl_xor_sync(0xFFFFFFFFu, s1, o);
    }
    if (lane == 0) {
        if (isQ) { g_qsq[warp] = s2; g_qsum[warp] = s1; }
        else     { g_psq[warp - QN] = s2; g_psum[warp - QN] = s1; }
    }
}

// load a (rows x 32 fp16) tile chunk into padded SMEM via cp.async
template<int ROWS, int PER_T>
__device__ __forceinline__ void load_tile(uint32_t dst_base, const unsigned short* src,
                                          int ch, int tid) {
    #pragma unroll
    for (int ii = 0; ii < PER_T; ii++) {
        int j = tid + ii * 256;
        int row = j >> 2, c = j & 3;
        cp16(dst_base + row * TSTRIDE + c * 16,
             src + (size_t)row * DN + ch * BKC + c * 8);
    }
}

// ============================================================
// 2) fp16 two-limb GEMM: main pass f32-acc, corrections f16-acc.
//    grid=(KN/BN, QN/BM), 256 threads (8 warps, 4x2), 2-stage cp.async.
// ============================================================
__global__ void __launch_bounds__(256, 2) tc_gemm_kernel(float* __restrict__ out) {
    extern __shared__ char smem[];
    const int bx = blockIdx.x, by = blockIdx.y;
    const int tid = threadIdx.x;
    const int wid = tid >> 5, lane = tid & 31;
    const int warp_m = wid & 3;         // 32-row band
    const int warp_n = wid >> 2;        // 32-col band
    const uint32_t sb = smem_to_u32(smem);

    if (tid < 128) {
        ((float*)(smem + SM_QSQ))[tid] = g_qsq[by * BM + tid];
        ((float*)(smem + SM_QSM))[tid] = g_qsum[by * BM + tid];
    }
    if (tid < 64) {
        ((float*)(smem + SM_PSQ))[tid] = g_psq[bx * BN + tid];
        ((float*)(smem + SM_PSM))[tid] = g_psum[bx * BN + tid];
    }

    const unsigned short* Ah = g_Qhi + (size_t)by * BM * DN;
    const unsigned short* Al = g_Qlo + (size_t)by * BM * DN;
    const unsigned short* Bh = g_Phi + (size_t)bx * BN * DN;
    const unsigned short* Bl = g_Plo + (size_t)bx * BN * DN;

    // prologue: chunks 0,1 into stages 0,1
    #pragma unroll
    for (int c = 0; c < 2; c++) {
        uint32_t st = sb + SM_TILES + c * STAGE_B;
        load_tile<128, 2>(st, Ah, c, tid);
        load_tile<128, 2>(st + TILE_A, Al, c, tid);
        load_tile<64, 1>(st + 2 * TILE_A, Bh, c, tid);
        load_tile<64, 1>(st + 2 * TILE_A + TILE_Bb, Bl, c, tid);
        CP_COMMIT();
    }

    float accM[2][4][4];
    uint32_t accC[2][4][2];
    #pragma unroll
    for (int t = 0; t < 2; t++)
        #pragma unroll
        for (int u = 0; u < 4; u++) {
            #pragma unroll
            for (int v = 0; v < 4; v++) accM[t][u][v] = 0.f;
            accC[t][u][0] = 0u; accC[t][u][1] = 0u;
        }

    for (int ch = 0; ch < NCH; ch++) {
        if (ch + 1 < NCH) { CP_WAIT(1); } else { CP_WAIT(0); }
        __syncthreads();

        const uint32_t base = sb + SM_TILES + (ch & 1) * STAGE_B;
        const uint32_t arow = warp_m * 32 + (lane & 15);
        const uint32_t brow = warp_n * 32 + (lane & 15);
        const uint32_t khalf = (lane >> 4) * 16;

        #pragma unroll
        for (int s = 0; s < 2; s++) {                // two k16 steps per chunk
            const uint32_t koff = s * 32 + khalf;
            uint32_t ah[2][4], al[2][4];
            #pragma unroll
            for (int t = 0; t < 2; t++) {
                ldm_x4(ah[t], base + (arow + t * 16) * TSTRIDE + koff);
                ldm_x4(al[t], base + TILE_A + (arow + t * 16) * TSTRIDE + koff);
            }
            #pragma unroll
            for (int np = 0; np < 2; np++) {         // 2 ntile-pairs (16 cols each)
                uint32_t bh[4], bl[4];
                ldm_x4(bh, base + 2 * TILE_A + (brow + np * 16) * TSTRIDE + koff);
                ldm_x4(bl, base + 2 * TILE_A + TILE_Bb + (brow + np * 16) * TSTRIDE + koff);
                #pragma unroll
                for (int t = 0; t < 2; t++) {
                    #pragma unroll
                    for (int q = 0; q < 2; q++) {
                        const int u = np * 2 + q;
                        mma_f32(accM[t][u], ah[t], bh[q], bh[2 + q]);   // hi*hi (f32 acc)
                        mma_f16(accC[t][u], ah[t], bl[q], bl[2 + q]);   // hi*lo (f16 acc)
                        mma_f16(accC[t][u], al[t], bh[q], bh[2 + q]);   // lo*hi (f16 acc)
                    }
                }
            }
        }
        __syncthreads();
        if (ch + 2 < NCH) {
            uint32_t st = sb + SM_TILES + (ch & 1) * STAGE_B;
            load_tile<128, 2>(st, Ah, ch + 2, tid);
            load_tile<128, 2>(st + TILE_A, Al, ch + 2, tid);
            load_tile<64, 1>(st + 2 * TILE_A, Bh, ch + 2, tid);
            load_tile<64, 1>(st + 2 * TILE_A + TILE_Bb, Bl, ch + 2, tid);
            CP_COMMIT();
        }
    }

    // ---------- fused epilogue ----------
    const float kconst = (float)DN * EPSF * EPSF;
    const float* sQSQ = (const float*)(smem + SM_QSQ);
    const float* sQSM = (const float*)(smem + SM_QSM);
    const float* sPSQ = (const float*)(smem + SM_PSQ);
    const float* sPSM = (const float*)(smem + SM_PSM);

    #pragma unroll
    for (int t = 0; t < 2; t++) {
        #pragma unroll
        for (int rr = 0; rr < 2; rr++) {
            const int rowl = warp_m * 32 + t * 16 + rr * 8 + (lane >> 2);
            const int grow = by * BM + rowl;
            const float qsq = sQSQ[rowl];
            const float qsm = sQSM[rowl];
            float su = 0.f, sud = 0.f, mu = 0.f;
            float* op = out + (size_t)grow * KN + bx * BN + warp_n * 32;
            #pragma unroll
            for (int u = 0; u < 4; u++) {
                const int c0 = u * 8 + (lane & 3) * 2;
                const int gc0 = warp_n * 32 + c0;
                float2 corr = __half22float2(*(__half2*)&accC[t][u][rr]);
                float cr0 = accM[t][u][rr * 2 + 0] + corr.x;
                float cr1 = accM[t][u][rr * 2 + 1] + corr.y;
                float sq0 = qsq + sPSQ[gc0]     - 2.f * cr0 + 2.f * EPSF * (qsm - sPSM[gc0])     + kconst;
                float sq1 = qsq + sPSQ[gc0 + 1] - 2.f * cr1 + 2.f * EPSF * (qsm - sPSM[gc0 + 1]) + kconst;
                float d0 = sqrtf(fmaxf(sq0, 0.f));
                float d1 = sqrtf(fmaxf(sq1, 0.f));
                float u0 = __expf(-d0);
                float u1 = __expf(-d1);
                su += u0 + u1;
                sud = fmaf(u0, d0, fmaf(u1, d1, sud));
                mu = fmaxf(mu, fmaxf(u0, u1));
                *(float2*)(op + c0) = make_float2(u0, u1);
            }
            #pragma unroll
            for (int o = 1; o <= 2; o <<= 1) {
                su  += __shfl_xor_sync(0xFFFFFFFFu, su,  o);
                sud += __shfl_xor_sync(0xFFFFFFFFu, sud, o);
                mu   = fmaxf(mu, __shfl_xor_sync(0xFFFFFFFFu, mu, o));
            }
            if ((lane & 3) == 0) {
                const size_t pidx = (size_t)grow * NPART + bx * 2 + warp_n;
                g_Spart[pidx] = su;
                g_Upart[pidx] = sud;
                g_Mpart[pidx] = mu;
            }
        }
    }
}

// ============================================================
// 3) Finalize: one block per query row, fixed-order reduction.
// ============================================================
__global__ __launch_bounds__(256) void finalize_kernel(float* __restrict__ out) {
    const int row = blockIdx.x;
    float S = 0.f, U = 0.f, Mx = 0.f;
    #pragma unroll
    for (int j = 0; j < NPART; j++) {
        S += g_Spart[(size_t)row * NPART + j];
        U += g_Upart[(size_t)row * NPART + j];
        Mx = fmaxf(Mx, g_Mpart[(size_t)row * NPART + j]);
    }
    const float invS = 1.f / S;

    float4* post4 = (float4*)(out + (size_t)row * KN);
    float4 v = post4[threadIdx.x];
    v.x *= invS; v.y *= invS; v.z *= invS; v.w *= invS;
    post4[threadIdx.x] = v;

    if (threadIdx.x == 0) {
        out[(size_t)QN * KN + row]      = Mx * invS;           // c
        out[(size_t)QN * KN + QN + row] = U * invS + logf(S);  // h
    }
}

// ============================================================
extern "C" void kernel_launch(void* const* d_in, const int* in_sizes, int n_in,
                              void* d_out, int out_size) {
    const float* P  = (const float*)d_in[0];   // class_prototypes [KN, DN]
    const float* Qf = (const float*)d_in[1];   // query_features   [QN, DN]
    float* out = (float*)d_out;

    {
        int blocks = ((QN + KN) * 32 + 255) / 256;
        convert_stats_kernel<<<blocks, 256>>>(Qf, P);
    }
    cudaFuncSetAttribute(tc_gemm_kernel, cudaFuncAttributeMaxDynamicSharedMemorySize, SMEM_TOTAL);
    {
        dim3 grid(KN / BN, QN / BM);
        tc_gemm_kernel<<<grid, 256, SMEM_TOTAL>>>(out);
    }
    finalize_kernel<<<QN, 256>>>(out);
}